// round 15
// baseline (speedup 1.0000x reference)
#include <cuda_runtime.h>
#include <cuda_bf16.h>

#define B_DIM 128
#define N_DIM 256
#define RSW   148      // P row stride (words): half0 @ +0 (64w), half1 @ +80 (64w)
#define ITERS 50
#define NTHR  512

#define W_PH   0
#define W_S    37888
#define W_BM   38144
#define W_GA   38400
#define W_U    38656
#define W_VA   38912                   // base % 32 == 0
#define W_VB   39184                   // base % 32 == 16
#define W_SP   39440                   // 8 x 256 column partials
#define W_RED  41488
#define W_EI   41520
#define W_PW   41776
#define W_AN   43824
#define SMEM_WORDS (W_AN + 32*256)     // 52016 words = 208064 B

__device__ float    g_sum = 0.f;
__device__ int      g_cnt = 0;
__device__ unsigned g_tk  = 0u;

typedef unsigned long long ull;

__device__ __forceinline__ float bf_lo(unsigned w) { return __int_as_float(w << 16); }
__device__ __forceinline__ float bf_hi(unsigned w) { return __int_as_float(w & 0xffff0000u); }
__device__ __forceinline__ void bffma2(ull& acc, unsigned w, ull m) {
    asm("{\n\t.reg .b32 lo, hi;\n\t.reg .b64 p;\n\t"
        "shl.b32 lo, %1, 16;\n\tand.b32 hi, %1, 0xffff0000;\n\t"
        "mov.b64 p, {lo, hi};\n\tfma.rn.f32x2 %0, p, %2, %0;\n\t}"
        : "+l"(acc) : "r"(w), "l"(m));
}
__device__ __forceinline__ float f2lo(ull a) { return __uint_as_float((unsigned)a); }
__device__ __forceinline__ float f2hi(ull a) { return __uint_as_float((unsigned)(a >> 32)); }

__global__ void __launch_bounds__(NTHR, 1)
mega_kernel(const float* __restrict__ yp, const int* __restrict__ ytr,
            float* __restrict__ out) {
    extern __shared__ unsigned smw[];
    unsigned* Pw = smw + W_PH;
    float* s   = (float*)(smw + W_S);
    float* Bm  = (float*)(smw + W_BM);
    float* gA  = (float*)(smw + W_GA);
    float* u   = (float*)(smw + W_U);
    float* vA  = (float*)(smw + W_VA);
    float* vB  = (float*)(smw + W_VB);
    float* sp  = (float*)(smw + W_SP);
    float* red = (float*)(smw + W_RED);
    int*   ei  = (int*)(smw + W_EI);
    float* pw  = (float*)(smw + W_PW);
    float* AN  = (float*)(smw + W_AN);

    const int tid  = threadIdx.x;
    const int b    = blockIdx.x;
    const int lane = tid & 31;
    const int wid  = tid >> 5;

    // ---- global min/max of y_true ----
    int shift;
    {
        const int4* t4 = (const int4*)ytr;
        unsigned umx = 0u, umn = 0u;
        #pragma unroll
        for (int k = 0; k < (B_DIM * N_DIM / 4) / NTHR; k++) {
            int4 x = t4[tid + k * NTHR];
            unsigned a0 = (unsigned)x.x ^ 0x80000000u, a1 = (unsigned)x.y ^ 0x80000000u;
            unsigned a2 = (unsigned)x.z ^ 0x80000000u, a3 = (unsigned)x.w ^ 0x80000000u;
            umx = max(umx, max(max(a0, a1), max(a2, a3)));
            umn = max(umn, max(max(~a0, ~a1), max(~a2, ~a3)));
        }
        for (int o = 16; o; o >>= 1) {
            umx = max(umx, __shfl_xor_sync(0xffffffffu, umx, o));
            umn = max(umn, __shfl_xor_sync(0xffffffffu, umn, o));
        }
        unsigned* ur = (unsigned*)red;
        if (lane == 0) { ur[wid] = umx; ur[16 + wid] = umn; }
        __syncthreads();
        if (tid == 0) {
            for (int k = 1; k < 16; k++) { umx = max(umx, ur[k]); umn = max(umn, ur[16 + k]); }
            ei[0] = (int)(umx ^ 0x80000000u) + (int)((~umn) ^ 0x80000000u);
        }
        __syncthreads();
        shift = ei[0];
        __syncthreads();
    }

    // ---- setup ----
    float sj = 0.f, gain = 0.f; int e = 0;
    if (tid < 256) {
        sj = yp[b * N_DIM + tid];
        s[tid] = sj;
        e = shift - ytr[b * N_DIM + tid];
        e = min(max(e, 0), 30);
        ei[tid] = e;
        gain = (float)((1u << e) - 1u);
        gA[tid] = gain;
        u[tid] = 1.0f;
    }
    __syncthreads();

    // ---- B_mat (Kahan) + IDCG ----
    float idcg = 0.f;
    if (tid < 256) {
        float bsum = 0.f, bc = 0.f;
        int pos = 0;
        for (int k = 0; k < N_DIM; k++) {
            float d  = fabsf(sj - s[k]);
            float y  = d - bc;
            float t2 = bsum + y;
            bc = (t2 - bsum) - y;
            bsum = t2;
            int ek = ei[k];
            pos += (ek > e) ? 1 : 0;
            pos += ((k < tid) && (ek == e)) ? 1 : 0;
        }
        Bm[tid] = bsum;
        float x = gain / log2f((float)(pos + 2));
        for (int o = 16; o; o >>= 1) x += __shfl_xor_sync(0xffffffffu, x, o);
        if (lane == 0) red[wid] = x;
    }
    __syncthreads();
    if (tid == 0) { for (int k = 0; k < 8; k++) idcg += red[k]; }

    // ==== P build (exp-free block scheme) ====
    if (tid < 256) {
        float r = __expf(-2.0f * sj);
        float pk = 1.0f;
        pw[tid] = 1.0f;
        #pragma unroll
        for (int k = 1; k < 8; k++) { pk *= r; pw[k * 256 + tid] = pk; }
    }
    for (int m = wid; m < 32; m += 16) {
        float sc = (float)(255 - 16 * m);
        float lg[8];
        float mxl = -3.4e38f;
        #pragma unroll
        for (int c = 0; c < 8; c++) {
            int j = c * 32 + lane;
            lg[c] = fmaf(s[j], sc, -Bm[j]);
            mxl = fmaxf(mxl, lg[c]);
        }
        for (int o = 16; o; o >>= 1) mxl = fmaxf(mxl, __shfl_xor_sync(0xffffffffu, mxl, o));
        float* an = AN + m * 256;
        #pragma unroll
        for (int c = 0; c < 8; c++) an[c * 32 + lane] = __expf(lg[c] - mxl);
    }
    __syncthreads();

    // fill: warp per row; c<2 -> word 32c+lane, c>=2 -> 32c+lane+16 (half1 @ +80)
    #pragma unroll 1
    for (int t = 0; t < 16; t++) {
        int i = wid + 16 * t;
        const float* an = AN + (i >> 3) * 256;
        const float* pk = pw + (i & 7) * 256;
        float f0[4], f1[4];
        float ssum = 0.f;
        #pragma unroll
        for (int c = 0; c < 4; c++) {
            float2 a2 = *(const float2*)(an + c * 64 + 2 * lane);
            float2 k2 = *(const float2*)(pk + c * 64 + 2 * lane);
            f0[c] = a2.x * k2.x;
            f1[c] = a2.y * k2.y;
            ssum += f0[c] + f1[c];
        }
        for (int o = 16; o; o >>= 1) ssum += __shfl_xor_sync(0xffffffffu, ssum, o);
        float inv = 1.0f / ssum;
        unsigned* row = Pw + (unsigned)i * RSW;
        #pragma unroll
        for (int c = 0; c < 4; c++) {
            __nv_bfloat162 pr = __floats2bfloat162_rn(f0[c] * inv, f1[c] * inv);
            row[c * 32 + lane + (c >= 2 ? 16 : 0)] = *(unsigned*)&pr;
        }
    }
    __syncthreads();

    // ---- Sinkhorn: 3 barriers/iter, 16-warp row pass ----
    const int o8 = tid >> 6;
    const int p4 = tid & 63;
    const unsigned coloff = 2u * (unsigned)p4 + ((unsigned)(p4 >> 5) << 4);
    const unsigned* colp = Pw + (unsigned)(o8 * 32) * RSW + coloff;
    const float* uo = u + o8 * 32;
    const int rr = tid >> 1, hh = tid & 1;
    const unsigned* prow = Pw + (unsigned)rr * RSW + 80u * (unsigned)hh;
    const float* vbase = hh ? (vB + 128) : vA;
    float ureg = 1.0f;
    float vprev = 0.f;

    for (int it = 0; it < ITERS; it++) {
        // column pass (identical math to R12)
        float a0 = 0.f, a1 = 0.f, a2 = 0.f, a3 = 0.f;
        #pragma unroll
        for (int ri = 0; ri < 8; ri++) {
            float4 uu = *(const float4*)(uo + 4 * ri);
            uint2 w0 = *(const uint2*)(colp + (4 * ri + 0) * RSW);
            uint2 w1 = *(const uint2*)(colp + (4 * ri + 1) * RSW);
            uint2 w2 = *(const uint2*)(colp + (4 * ri + 2) * RSW);
            uint2 w3 = *(const uint2*)(colp + (4 * ri + 3) * RSW);
            a0 = fmaf(bf_lo(w0.x), uu.x, a0); a1 = fmaf(bf_hi(w0.x), uu.x, a1);
            a2 = fmaf(bf_lo(w0.y), uu.x, a2); a3 = fmaf(bf_hi(w0.y), uu.x, a3);
            a0 = fmaf(bf_lo(w1.x), uu.y, a0); a1 = fmaf(bf_hi(w1.x), uu.y, a1);
            a2 = fmaf(bf_lo(w1.y), uu.y, a2); a3 = fmaf(bf_hi(w1.y), uu.y, a3);
            a0 = fmaf(bf_lo(w2.x), uu.z, a0); a1 = fmaf(bf_hi(w2.x), uu.z, a1);
            a2 = fmaf(bf_lo(w2.y), uu.z, a2); a3 = fmaf(bf_hi(w2.y), uu.z, a3);
            a0 = fmaf(bf_lo(w3.x), uu.w, a0); a1 = fmaf(bf_hi(w3.x), uu.w, a1);
            a2 = fmaf(bf_lo(w3.y), uu.w, a2); a3 = fmaf(bf_hi(w3.y), uu.w, a3);
        }
        *(float4*)(sp + o8 * 256 + 4 * p4) = make_float4(a0, a1, a2, a3);
        __syncthreads();

        // v update: dual store vA/vB (threads 0..255)
        int ch = 0;
        if (tid < 256) {
            float S = ((sp[tid] + sp[256 + tid]) + (sp[512 + tid] + sp[768 + tid]))
                    + ((sp[1024 + tid] + sp[1280 + tid]) + (sp[1536 + tid] + sp[1792 + tid]));
            float vn = 1.0f / fmaxf(S, 1e-10f);
            vA[tid] = vn;
            vB[tid] = vn;
            ch = (fabsf(vn - vprev) > 1e-4f * fabsf(vprev)) ? 1 : 0;
            vprev = vn;
        }
        if (__syncthreads_or(ch) == 0) break;

        // row pass: half-row per thread (all 512), FFMA2, shfl-pair combine
        {
            ull c0 = 0ull, c1 = 0ull, c2 = 0ull, c3 = 0ull;
            #pragma unroll
            for (int jj = 0; jj < 16; jj++) {
                uint4 pq = *(const uint4*)(prow + 4 * jj);
                ull m0 = *(const ull*)(vbase + 8 * jj);
                ull m1 = *(const ull*)(vbase + 8 * jj + 2);
                ull m2 = *(const ull*)(vbase + 8 * jj + 4);
                ull m3 = *(const ull*)(vbase + 8 * jj + 6);
                bffma2(c0, pq.x, m0); bffma2(c1, pq.y, m1);
                bffma2(c2, pq.z, m2); bffma2(c3, pq.w, m3);
            }
            float dot = ((f2lo(c0) + f2hi(c0)) + (f2lo(c1) + f2hi(c1)))
                      + ((f2lo(c2) + f2hi(c2)) + (f2lo(c3) + f2hi(c3)));
            dot += __shfl_xor_sync(0xffffffffu, dot, 1);
            if (hh == 0) {
                ureg = 1.0f / fmaxf(dot, 1e-10f);
                u[rr] = ureg;
            }
        }
        __syncthreads();
    }

    // ---- final contraction ----
    if (tid < 256) {
        float wv = vA[tid] * gA[tid];
        vA[tid] = wv;
        vB[tid] = wv;
    }
    __syncthreads();
    {
        ull c0 = 0ull, c1 = 0ull, c2 = 0ull, c3 = 0ull;
        #pragma unroll
        for (int jj = 0; jj < 16; jj++) {
            uint4 pq = *(const uint4*)(prow + 4 * jj);
            ull m0 = *(const ull*)(vbase + 8 * jj);
            ull m1 = *(const ull*)(vbase + 8 * jj + 2);
            ull m2 = *(const ull*)(vbase + 8 * jj + 4);
            ull m3 = *(const ull*)(vbase + 8 * jj + 6);
            bffma2(c0, pq.x, m0); bffma2(c1, pq.y, m1);
            bffma2(c2, pq.z, m2); bffma2(c3, pq.w, m3);
        }
        float dot = ((f2lo(c0) + f2hi(c0)) + (f2lo(c1) + f2hi(c1)))
                  + ((f2lo(c2) + f2hi(c2)) + (f2lo(c3) + f2hi(c3)));
        dot += __shfl_xor_sync(0xffffffffu, dot, 1);
        float val = (hh == 0) ? (ureg * dot / log2f((float)(rr + 2))) : 0.0f;
        for (int o = 16; o; o >>= 1) val += __shfl_xor_sync(0xffffffffu, val, o);
        if (lane == 0) red[wid] = val;
    }
    __syncthreads();

    // ---- fused global reduction ----
    if (tid == 0) {
        float num = 0.f;
        for (int k = 0; k < 16; k++) num += red[k];
        bool valid = (idcg != 0.0f);
        float nd = valid ? (num / (idcg + 1e-10f)) : 0.0f;
        atomicAdd(&g_sum, nd);
        atomicAdd(&g_cnt, valid ? 1 : 0);
        __threadfence();
        unsigned tk = atomicAdd(&g_tk, 1u);
        if (tk == (unsigned)(B_DIM - 1)) {
            float sm = atomicAdd(&g_sum, 0.0f);
            int   c  = atomicAdd(&g_cnt, 0);
            out[0] = (c > 0) ? (-(sm / (float)c)) : 0.0f;
            g_sum = 0.f;
            g_cnt = 0;
            __threadfence();
            g_tk = 0u;
        }
    }
}

extern "C" void kernel_launch(void* const* d_in, const int* in_sizes, int n_in,
                              void* d_out, int out_size) {
    const float* yp  = (const float*)d_in[0];
    const int*   ytr = (const int*)d_in[1];
    float*       out = (float*)d_out;
    size_t smem = (size_t)SMEM_WORDS * 4;   // 208064 B
    cudaFuncSetAttribute(mega_kernel, cudaFuncAttributeMaxDynamicSharedMemorySize, (int)smem);
    mega_kernel<<<B_DIM, NTHR, smem>>>(yp, ytr, out);
}

// round 16
// speedup vs baseline: 1.1559x; 1.1559x over previous
#include <cuda_runtime.h>
#include <cuda_bf16.h>

#define B_DIM 128
#define N_DIM 256
#define RSW   132                  // P row stride in words: even, %4==0 -> LDS.128 rows
#define ITERS 50
#define NTHR  512

// ---- smem word offsets ----
#define W_PH   0                       // 33792 : P bf16 padded rows (256 x 132)
#define W_S    33792
#define W_BM   34048
#define W_GA   34304
#define W_U    34560
#define W_V    34816
#define W_W    35072
#define W_SP   35328                   // 4096 : 16 x 256 column partials
#define W_RED  39424                   // 32
#define W_EI   39456                   // 256
#define W_PW   39712                   // 8*256 : r^k tables
#define W_AN   41760                   // 32*256 : anchor rows
#define SMEM_WORDS (W_AN + 32*256)     // 49952 words = 199808 B

__device__ float    g_sum = 0.f;
__device__ int      g_cnt = 0;
__device__ unsigned g_tk  = 0u;

__device__ __forceinline__ float bf_lo(unsigned w) { return __int_as_float(w << 16); }
__device__ __forceinline__ float bf_hi(unsigned w) { return __int_as_float(w & 0xffff0000u); }

// ------------------------------------------------------------- mega kernel ---
__global__ void __launch_bounds__(NTHR, 1)
mega_kernel(const float* __restrict__ yp, const int* __restrict__ ytr,
            float* __restrict__ out) {
    extern __shared__ unsigned smw[];
    unsigned* Pw = smw + W_PH;
    float* s   = (float*)(smw + W_S);
    float* Bm  = (float*)(smw + W_BM);
    float* gA  = (float*)(smw + W_GA);
    float* u   = (float*)(smw + W_U);
    float* v   = (float*)(smw + W_V);
    float* w   = (float*)(smw + W_W);
    float* sp  = (float*)(smw + W_SP);
    float* red = (float*)(smw + W_RED);
    int*   ei  = (int*)(smw + W_EI);
    float* pw  = (float*)(smw + W_PW);
    float* AN  = (float*)(smw + W_AN);

    const int tid  = threadIdx.x;
    const int b    = blockIdx.x;
    const int lane = tid & 31;
    const int wid  = tid >> 5;

    // ---- fused global min/max of y_true (L2-hot scan) ----
    int shift;
    {
        const int4* t4 = (const int4*)ytr;
        unsigned umx = 0u, umn = 0u;
        #pragma unroll
        for (int k = 0; k < (B_DIM * N_DIM / 4) / NTHR; k++) {
            int4 x = t4[tid + k * NTHR];
            unsigned a0 = (unsigned)x.x ^ 0x80000000u, a1 = (unsigned)x.y ^ 0x80000000u;
            unsigned a2 = (unsigned)x.z ^ 0x80000000u, a3 = (unsigned)x.w ^ 0x80000000u;
            umx = max(umx, max(max(a0, a1), max(a2, a3)));
            umn = max(umn, max(max(~a0, ~a1), max(~a2, ~a3)));
        }
        for (int o = 16; o; o >>= 1) {
            umx = max(umx, __shfl_xor_sync(0xffffffffu, umx, o));
            umn = max(umn, __shfl_xor_sync(0xffffffffu, umn, o));
        }
        unsigned* ur = (unsigned*)red;
        if (lane == 0) { ur[wid] = umx; ur[16 + wid] = umn; }
        __syncthreads();
        if (tid == 0) {
            for (int k = 1; k < 16; k++) { umx = max(umx, ur[k]); umn = max(umn, ur[16 + k]); }
            red[31] = __int_as_float((int)(umx ^ 0x80000000u) + (int)((~umn) ^ 0x80000000u));
        }
        __syncthreads();
        shift = __float_as_int(red[31]);
    }

    // ---- setup: scores, flipped relevancy, gains ----
    if (tid < 256) {
        float sv = yp[b * N_DIM + tid];
        s[tid] = sv;
        int e = shift - ytr[b * N_DIM + tid];
        e = min(max(e, 0), 30);
        ei[tid] = e;
        gA[tid] = (float)((1u << e) - 1u);
        u[tid] = 1.0f;
    }
    __syncthreads();

    // ---- B_mat + IDCG rank: split across all 512 threads (k-range halves) ----
    {
        const int row   = tid & 255;
        const int kbase = (tid >> 8) * 128;
        const float sr  = s[row];
        const int   er  = ei[row];
        float b0 = 0.f, b1 = 0.f;
        int pos = 0;
        #pragma unroll 8
        for (int k = 0; k < 128; k += 4) {
            float4 s4 = *(const float4*)(s + kbase + k);
            int4   e4 = *(const int4*)(ei + kbase + k);
            b0 += fabsf(sr - s4.x); b1 += fabsf(sr - s4.y);
            b0 += fabsf(sr - s4.z); b1 += fabsf(sr - s4.w);
            int kk = kbase + k;
            pos += ((e4.x > er) ? 1 : 0) + (((kk     < row) && (e4.x == er)) ? 1 : 0);
            pos += ((e4.y > er) ? 1 : 0) + (((kk + 1 < row) && (e4.y == er)) ? 1 : 0);
            pos += ((e4.z > er) ? 1 : 0) + (((kk + 2 < row) && (e4.z == er)) ? 1 : 0);
            pos += ((e4.w > er) ? 1 : 0) + (((kk + 3 < row) && (e4.w == er)) ? 1 : 0);
        }
        sp[tid] = b0 + b1;
        ((int*)sp)[512 + tid] = pos;
    }
    __syncthreads();
    float idcg = 0.f;
    if (tid < 256) {
        Bm[tid] = sp[tid] + sp[256 + tid];
        int pos = ((int*)sp)[512 + tid] + ((int*)sp)[768 + tid];
        float x = gA[tid] / log2f((float)(pos + 2));
        for (int o = 16; o; o >>= 1) x += __shfl_xor_sync(0xffffffffu, x, o);
        if (lane == 0) red[wid] = x;
    }
    __syncthreads();
    if (tid == 0) { for (int k = 0; k < 8; k++) idcg += red[k]; }

    // ==== P build (exp-free block scheme) ====
    if (tid < 256) {
        float r = __expf(-2.0f * s[tid]);
        float pk = 1.0f;
        pw[tid] = 1.0f;
        #pragma unroll
        for (int k = 1; k < 8; k++) { pk *= r; pw[k * 256 + tid] = pk; }
    }
    for (int m = wid; m < 32; m += 16) {
        float sc = (float)(255 - 16 * m);
        float lg[8];
        float mxl = -3.4e38f;
        #pragma unroll
        for (int c = 0; c < 8; c++) {
            int j = c * 32 + lane;
            lg[c] = fmaf(s[j], sc, -Bm[j]);
            mxl = fmaxf(mxl, lg[c]);
        }
        for (int o = 16; o; o >>= 1) mxl = fmaxf(mxl, __shfl_xor_sync(0xffffffffu, mxl, o));
        float* an = AN + m * 256;
        #pragma unroll
        for (int c = 0; c < 8; c++) an[c * 32 + lane] = __expf(lg[c] - mxl);
    }
    __syncthreads();

    // fill: warp per row; lane handles col pairs (64c+2lane, +1), c=0..3
    #pragma unroll 2
    for (int t = 0; t < 16; t++) {
        int i = wid + 16 * t;
        const float* an = AN + (i >> 3) * 256;
        const float* pk = pw + (i & 7) * 256;
        float f0[4], f1[4];
        float ssum = 0.f;
        #pragma unroll
        for (int c = 0; c < 4; c++) {
            float2 a2 = *(const float2*)(an + c * 64 + 2 * lane);
            float2 k2 = *(const float2*)(pk + c * 64 + 2 * lane);
            f0[c] = a2.x * k2.x;
            f1[c] = a2.y * k2.y;
            ssum += f0[c] + f1[c];
        }
        for (int o = 16; o; o >>= 1) ssum += __shfl_xor_sync(0xffffffffu, ssum, o);
        float inv = 1.0f / ssum;
        unsigned* row = Pw + (unsigned)i * RSW;
        #pragma unroll
        for (int c = 0; c < 4; c++) {
            __nv_bfloat162 pr = __floats2bfloat162_rn(f0[c] * inv, f1[c] * inv);
            row[c * 32 + lane] = *(unsigned*)&pr;
        }
    }
    __syncthreads();

    // ---- Sinkhorn, fixed 50 iterations, 3 barriers/iter ----
    const int cg = tid & 31;                          // col group: cols 8cg..8cg+7
    const int rg = tid >> 5;                          // row group: rows 16rg..16rg+15
    const unsigned* colp = Pw + (unsigned)(rg * 16) * RSW + 4u * (unsigned)cg;
    const float* uo = u + rg * 16;
    const unsigned* rowp = Pw + (unsigned)tid * RSW;  // full row for tid < 256

    for (int it = 0; it < ITERS; it++) {
        // column pass: 16 rows x 8 cols per thread (LDS.128 on P)
        float a0 = 0.f, a1 = 0.f, a2 = 0.f, a3 = 0.f;
        float a4 = 0.f, a5 = 0.f, a6 = 0.f, a7 = 0.f;
        #pragma unroll
        for (int q = 0; q < 4; q++) {
            float4 uu = *(const float4*)(uo + 4 * q);
            uint4 w0 = *(const uint4*)(colp + (4 * q + 0) * RSW);
            uint4 w1 = *(const uint4*)(colp + (4 * q + 1) * RSW);
            uint4 w2 = *(const uint4*)(colp + (4 * q + 2) * RSW);
            uint4 w3 = *(const uint4*)(colp + (4 * q + 3) * RSW);
            a0 = fmaf(bf_lo(w0.x), uu.x, a0); a1 = fmaf(bf_hi(w0.x), uu.x, a1);
            a2 = fmaf(bf_lo(w0.y), uu.x, a2); a3 = fmaf(bf_hi(w0.y), uu.x, a3);
            a4 = fmaf(bf_lo(w0.z), uu.x, a4); a5 = fmaf(bf_hi(w0.z), uu.x, a5);
            a6 = fmaf(bf_lo(w0.w), uu.x, a6); a7 = fmaf(bf_hi(w0.w), uu.x, a7);
            a0 = fmaf(bf_lo(w1.x), uu.y, a0); a1 = fmaf(bf_hi(w1.x), uu.y, a1);
            a2 = fmaf(bf_lo(w1.y), uu.y, a2); a3 = fmaf(bf_hi(w1.y), uu.y, a3);
            a4 = fmaf(bf_lo(w1.z), uu.y, a4); a5 = fmaf(bf_hi(w1.z), uu.y, a5);
            a6 = fmaf(bf_lo(w1.w), uu.y, a6); a7 = fmaf(bf_hi(w1.w), uu.y, a7);
            a0 = fmaf(bf_lo(w2.x), uu.z, a0); a1 = fmaf(bf_hi(w2.x), uu.z, a1);
            a2 = fmaf(bf_lo(w2.y), uu.z, a2); a3 = fmaf(bf_hi(w2.y), uu.z, a3);
            a4 = fmaf(bf_lo(w2.z), uu.z, a4); a5 = fmaf(bf_hi(w2.z), uu.z, a5);
            a6 = fmaf(bf_lo(w2.w), uu.z, a6); a7 = fmaf(bf_hi(w2.w), uu.z, a7);
            a0 = fmaf(bf_lo(w3.x), uu.w, a0); a1 = fmaf(bf_hi(w3.x), uu.w, a1);
            a2 = fmaf(bf_lo(w3.y), uu.w, a2); a3 = fmaf(bf_hi(w3.y), uu.w, a3);
            a4 = fmaf(bf_lo(w3.z), uu.w, a4); a5 = fmaf(bf_hi(w3.z), uu.w, a5);
            a6 = fmaf(bf_lo(w3.w), uu.w, a6); a7 = fmaf(bf_hi(w3.w), uu.w, a7);
        }
        float* spw = sp + rg * 256 + 8 * cg;
        *(float4*)(spw)     = make_float4(a0, a1, a2, a3);
        *(float4*)(spw + 4) = make_float4(a4, a5, a6, a7);
        __syncthreads();

        // v update (threads 0..255): sum 16 partials
        if (tid < 256) {
            float s0 = 0.f, s1 = 0.f, s2 = 0.f, s3 = 0.f;
            #pragma unroll
            for (int g = 0; g < 16; g += 4) {
                s0 += sp[(g + 0) * 256 + tid];
                s1 += sp[(g + 1) * 256 + tid];
                s2 += sp[(g + 2) * 256 + tid];
                s3 += sp[(g + 3) * 256 + tid];
            }
            float S = (s0 + s1) + (s2 + s3);
            v[tid] = 1.0f / fmaxf(S, 1e-10f);
        }
        __syncthreads();

        // row pass: full-row dot with v (256 threads), u in-thread
        if (tid < 256) {
            float r0 = 0.f, r1 = 0.f, r2 = 0.f, r3 = 0.f;
            #pragma unroll
            for (int j4 = 0; j4 < 32; j4++) {
                float4 v0 = *(const float4*)(v + 8 * j4);
                float4 v1 = *(const float4*)(v + 8 * j4 + 4);
                uint4 pq = *(const uint4*)(rowp + 4 * j4);
                r0 = fmaf(bf_lo(pq.x), v0.x, r0); r1 = fmaf(bf_hi(pq.x), v0.y, r1);
                r2 = fmaf(bf_lo(pq.y), v0.z, r2); r3 = fmaf(bf_hi(pq.y), v0.w, r3);
                r0 = fmaf(bf_lo(pq.z), v1.x, r0); r1 = fmaf(bf_hi(pq.z), v1.y, r1);
                r2 = fmaf(bf_lo(pq.w), v1.z, r2); r3 = fmaf(bf_hi(pq.w), v1.w, r3);
            }
            u[tid] = 1.0f / fmaxf((r0 + r1) + (r2 + r3), 1e-10f);
        }
        __syncthreads();
    }

    // ---- final: num = sum_i disc_i * u_i * (P[i] . (v*g)) ----
    if (tid < 256) w[tid] = v[tid] * gA[tid];
    __syncthreads();
    if (tid < 256) {
        float r0 = 0.f, r1 = 0.f, r2 = 0.f, r3 = 0.f;
        #pragma unroll
        for (int j4 = 0; j4 < 32; j4++) {
            float4 v0 = *(const float4*)(w + 8 * j4);
            float4 v1 = *(const float4*)(w + 8 * j4 + 4);
            uint4 pq = *(const uint4*)(rowp + 4 * j4);
            r0 = fmaf(bf_lo(pq.x), v0.x, r0); r1 = fmaf(bf_hi(pq.x), v0.y, r1);
            r2 = fmaf(bf_lo(pq.y), v0.z, r2); r3 = fmaf(bf_hi(pq.y), v0.w, r3);
            r0 = fmaf(bf_lo(pq.z), v1.x, r0); r1 = fmaf(bf_hi(pq.z), v1.y, r1);
            r2 = fmaf(bf_lo(pq.w), v1.z, r2); r3 = fmaf(bf_hi(pq.w), v1.w, r3);
        }
        float dot = (r0 + r1) + (r2 + r3);
        float val = u[tid] * dot / log2f((float)(tid + 2));
        for (int o = 16; o; o >>= 1) val += __shfl_xor_sync(0xffffffffu, val, o);
        if (lane == 0) red[wid] = val;
    }
    __syncthreads();

    // ---- fused global reduction (atomic ticket; last CTA writes output) ----
    if (tid == 0) {
        float num = 0.f;
        for (int k = 0; k < 8; k++) num += red[k];
        bool valid = (idcg != 0.0f);
        float nd = valid ? (num / (idcg + 1e-10f)) : 0.0f;
        atomicAdd(&g_sum, nd);
        atomicAdd(&g_cnt, valid ? 1 : 0);
        __threadfence();
        unsigned tk = atomicAdd(&g_tk, 1u);
        if (tk == (unsigned)(B_DIM - 1)) {
            float sm = atomicAdd(&g_sum, 0.0f);
            int   c  = atomicAdd(&g_cnt, 0);
            out[0] = (c > 0) ? (-(sm / (float)c)) : 0.0f;
            g_sum = 0.f;
            g_cnt = 0;
            __threadfence();
            g_tk = 0u;
        }
    }
}

// ------------------------------------------------------------------ launch ---
extern "C" void kernel_launch(void* const* d_in, const int* in_sizes, int n_in,
                              void* d_out, int out_size) {
    const float* yp  = (const float*)d_in[0];
    const int*   ytr = (const int*)d_in[1];
    float*       out = (float*)d_out;

    size_t smem = (size_t)SMEM_WORDS * 4;   // 199808 B
    cudaFuncSetAttribute(mega_kernel, cudaFuncAttributeMaxDynamicSharedMemorySize, (int)smem);
    mega_kernel<<<B_DIM, NTHR, smem>>>(yp, ytr, out);
}